// round 13
// baseline (speedup 1.0000x reference)
#include <cuda_runtime.h>
#include <math.h>
#include <stdint.h>

#define B_    16
#define N_    1024
#define H_    256
#define NT_   (B_ * N_)
#define F2_   512
#define ALPHA_ 0.3f

// ---------------- scratch ---------------------------------------------------
__device__ float g_dist[(size_t)B_ * N_ * N_];   // 64 MB
__device__ float g_n2[NT_];
__device__ int   g_parent[NT_];
__device__ float g_w[NT_];
__device__ float g_deg[NT_];
__device__ float g_dinv[NT_];
__device__ float g_prop[(size_t)NT_ * F2_];      // 32 MB
__device__ float g_bufA[(size_t)NT_ * F2_];      // 32 MB
__device__ float g_bufB[(size_t)NT_ * F2_];      // 32 MB
__device__ float g_Xhi[(size_t)NT_ * H_];        // 16 MB (tf32-split features)
__device__ float g_Xlo[(size_t)NT_ * H_];        // 16 MB
__device__ float g_WThi[F2_ * F2_];              // WT[N][K]
__device__ float g_WTlo[F2_ * F2_];
__device__ float g_pooled[B_ * F2_];
__device__ int   g_cnt[NT_];                     // children counts
__device__ int   g_fill[NT_];
__device__ int   g_off[NT_];                     // global CSR offsets
__device__ int   g_child[NT_];                   // children (global ids)

// ---------------- helpers ----------------------------------------------------
__device__ __forceinline__ uint32_t smem_u32(const void* p) {
    uint32_t a;
    asm("{ .reg .u64 t; cvta.to.shared.u64 t, %1; cvt.u32.u64 %0, t; }" : "=r"(a) : "l"(p));
    return a;
}
__device__ __forceinline__ float tf32_rna(float v) {
    uint32_t r;
    asm("cvt.rna.tf32.f32 %0, %1;" : "=r"(r) : "f"(v));
    return __uint_as_float(r);
}
__device__ __forceinline__ uint32_t redux_min_u32(uint32_t v) {
    uint32_t r;
    asm("redux.sync.min.u32 %0, %1, 0xffffffff;" : "=r"(r) : "r"(v));
    return r;
}
#define CP16(dst, src) asm volatile("cp.async.cg.shared.global [%0], [%1], 16;" :: "r"(dst), "l"(src))
#define CP_COMMIT()    asm volatile("cp.async.commit_group;" ::: "memory")
#define CP_WAIT1()     asm volatile("cp.async.wait_group 1;" ::: "memory")
#define CP_WAIT0()     asm volatile("cp.async.wait_group 0;" ::: "memory")

#define MMA_TF32(d, a, b) \
    asm volatile("mma.sync.aligned.m16n8k8.row.col.f32.tf32.tf32.f32 " \
        "{%0,%1,%2,%3}, {%4,%5,%6,%7}, {%8,%9}, {%0,%1,%2,%3};" \
        : "+f"((d)[0]), "+f"((d)[1]), "+f"((d)[2]), "+f"((d)[3]) \
        : "r"((a)[0]), "r"((a)[1]), "r"((a)[2]), "r"((a)[3]), "r"((b)[0]), "r"((b)[1]))

__device__ __forceinline__ uint32_t tile_ld(const uint32_t* base, int row, int k) {
    return base[row * 32 + (((k >> 2) ^ (row & 7)) << 2) + (k & 3)];
}

#define KC_ 32
#define STG_FLOATS 16384
#define GEMM_SMEM  (2 * STG_FLOATS * 4)

__device__ __forceinline__ void mma_stage_compute(
    const uint32_t* st, int lane, int wm, int wn, float acc[4][4][4]) {
    const uint32_t* sAhi = st;
    const uint32_t* sAlo = st + 4096;
    const uint32_t* sWhi = st + 8192;
    const uint32_t* sWlo = st + 12288;
    #pragma unroll
    for (int kk = 0; kk < 4; kk++) {
        int ck = kk * 8 + (lane & 3);
        uint32_t ah[4][4], al[4][4];
        #pragma unroll
        for (int mt = 0; mt < 4; mt++) {
            int m = wm + mt * 16 + (lane >> 2);
            ah[mt][0] = tile_ld(sAhi, m,     ck);
            ah[mt][1] = tile_ld(sAhi, m + 8, ck);
            ah[mt][2] = tile_ld(sAhi, m,     ck + 4);
            ah[mt][3] = tile_ld(sAhi, m + 8, ck + 4);
            al[mt][0] = tile_ld(sAlo, m,     ck);
            al[mt][1] = tile_ld(sAlo, m + 8, ck);
            al[mt][2] = tile_ld(sAlo, m,     ck + 4);
            al[mt][3] = tile_ld(sAlo, m + 8, ck + 4);
        }
        uint32_t bh[4][2], bl[4][2];
        #pragma unroll
        for (int nt = 0; nt < 4; nt++) {
            int n = wn + nt * 8 + (lane >> 2);
            bh[nt][0] = tile_ld(sWhi, n, ck);
            bh[nt][1] = tile_ld(sWhi, n, ck + 4);
            bl[nt][0] = tile_ld(sWlo, n, ck);
            bl[nt][1] = tile_ld(sWlo, n, ck + 4);
        }
        #pragma unroll
        for (int mt = 0; mt < 4; mt++)
            #pragma unroll
            for (int nt = 0; nt < 4; nt++) {
                MMA_TF32(acc[mt][nt], ah[mt], bh[nt]);
                MMA_TF32(acc[mt][nt], ah[mt], bl[nt]);
                MMA_TF32(acc[mt][nt], al[mt], bh[nt]);
            }
    }
}

// ---------------- row norms -------------------------------------------------
__global__ void norms_kernel(const float* __restrict__ X, int row0) {
    int row  = row0 + blockIdx.x * 8 + (threadIdx.x >> 5);
    int lane = threadIdx.x & 31;
    const float* r = X + (size_t)row * H_;
    float s = 0.f;
    #pragma unroll
    for (int i = lane; i < H_; i += 32) { float v = r[i]; s += v * v; }
    #pragma unroll
    for (int o = 16; o; o >>= 1) s += __shfl_down_sync(0xffffffffu, s, o);
    if (lane == 0) g_n2[row] = s;
}

// ---------------- features tf32 split ---------------------------------------
__global__ void xsplit(const float* __restrict__ X) {
    size_t i = (size_t)blockIdx.x * 256 + threadIdx.x;
    if (i >= (size_t)NT_ * H_ / 4) return;
    float4 v = ((const float4*)X)[i];
    float4 hi, lo;
    hi.x = tf32_rna(v.x); lo.x = v.x - hi.x;
    hi.y = tf32_rna(v.y); lo.y = v.y - hi.y;
    hi.z = tf32_rna(v.z); lo.z = v.z - hi.z;
    hi.w = tf32_rna(v.w); lo.w = v.w - hi.w;
    ((float4*)g_Xhi)[i] = hi;
    ((float4*)g_Xlo)[i] = lo;
}

// ---------------- distance matrix via 3xTF32 MMA ----------------------------
__global__ __launch_bounds__(256) void dist_mma() {
    if (blockIdx.x > blockIdx.y) return;
    extern __shared__ float smem[];
    uint32_t sb = smem_u32(smem);
    int b = blockIdx.z;
    int tid = threadIdx.x, lane = tid & 31, wid = tid >> 5;
    int bm = blockIdx.y * 128, bn = blockIdx.x * 128;
    int wm = (wid >> 2) * 64, wn = (wid & 3) * 32;
    size_t rowA = (size_t)b * N_ + bm;
    size_t rowB = (size_t)b * N_ + bn;
    int nc = H_ / KC_;

    int lrow[4], lk4[4];
    uint32_t ldoff[4];
    #pragma unroll
    for (int i = 0; i < 4; i++) {
        int lin = tid + i * 256;
        lrow[i] = lin >> 3; lk4[i] = lin & 7;
        ldoff[i] = (uint32_t)(lrow[i] * 128 + ((lk4[i] ^ (lrow[i] & 7)) << 4));
    }

    #define LOAD_CHUNK_D(c, s) do {                                            \
        uint32_t base = sb + (s) * (STG_FLOATS * 4);                           \
        _Pragma("unroll")                                                      \
        for (int i = 0; i < 4; i++) {                                          \
            size_t ga = (rowA + lrow[i]) * H_ + (c) * KC_ + lk4[i] * 4;        \
            size_t gb = (rowB + lrow[i]) * H_ + (c) * KC_ + lk4[i] * 4;        \
            CP16(base +         ldoff[i], g_Xhi + ga);                         \
            CP16(base + 16384 + ldoff[i], g_Xlo + ga);                         \
            CP16(base + 32768 + ldoff[i], g_Xhi + gb);                         \
            CP16(base + 49152 + ldoff[i], g_Xlo + gb);                         \
        }                                                                      \
        CP_COMMIT();                                                           \
    } while (0)

    float acc[4][4][4] = {};
    LOAD_CHUNK_D(0, 0);
    for (int c = 0; c < nc; c++) {
        if (c + 1 < nc) { LOAD_CHUNK_D(c + 1, (c + 1) & 1); CP_WAIT1(); }
        else            { CP_WAIT0(); }
        __syncthreads();
        mma_stage_compute((const uint32_t*)(smem + (c & 1) * STG_FLOATS), lane, wm, wn, acc);
        __syncthreads();
    }

    const float* n2b = g_n2 + b * N_;
    float* Db = g_dist + (size_t)b * N_ * N_;
    #pragma unroll
    for (int mt = 0; mt < 4; mt++) {
        int r0 = bm + wm + mt * 16 + (lane >> 2);
        float ni0 = n2b[r0], ni1 = n2b[r0 + 8];
        #pragma unroll
        for (int nt = 0; nt < 4; nt++) {
            int cb = bn + wn + nt * 8 + 2 * (lane & 3);
            float nj0 = n2b[cb], nj1 = n2b[cb + 1];
            float d00 = sqrtf(fmaxf(ni0 + nj0 - 2.0f * acc[mt][nt][0], 0.0f));
            float d01 = sqrtf(fmaxf(ni0 + nj1 - 2.0f * acc[mt][nt][1], 0.0f));
            float d10 = sqrtf(fmaxf(ni1 + nj0 - 2.0f * acc[mt][nt][2], 0.0f));
            float d11 = sqrtf(fmaxf(ni1 + nj1 - 2.0f * acc[mt][nt][3], 0.0f));
            *(float2*)&Db[(size_t)r0 * N_ + cb]       = make_float2(d00, d01);
            *(float2*)&Db[(size_t)(r0 + 8) * N_ + cb] = make_float2(d10, d11);
            if (blockIdx.x != blockIdx.y) {
                Db[(size_t)cb * N_ + r0]           = d00;
                Db[(size_t)(cb + 1) * N_ + r0]     = d01;
                Db[(size_t)cb * N_ + r0 + 8]       = d10;
                Db[(size_t)(cb + 1) * N_ + r0 + 8] = d11;
            }
        }
    }
}

// ---------------- Prim MST (R9 config: 128 thr, L1 prefetch) -----------------
__device__ __forceinline__ void warp_argmin_(float bv, int bi, float& wv, int& wi) {
    uint32_t vb = __float_as_uint(bv);
    uint32_t wmin = redux_min_u32(vb);
    uint32_t m = __ballot_sync(0xffffffffu, vb == wmin);
    int src = __ffs(m) - 1;
    wv = __uint_as_float(wmin);
    wi = __shfl_sync(0xffffffffu, bi, src);
}
__device__ __forceinline__ void prefetch_row_(const float* D, int v, int lane) {
    if ((unsigned)v >= (unsigned)N_) return;
    const char* p = (const char*)(D + (size_t)v * N_) + lane * 32;
    asm volatile("prefetch.global.L1 [%0];" :: "l"(p));
    asm volatile("prefetch.global.L1 [%0];" :: "l"(p + 1024));
    asm volatile("prefetch.global.L1 [%0];" :: "l"(p + 2048));
    asm volatile("prefetch.global.L1 [%0];" :: "l"(p + 3072));
}

__global__ __launch_bounds__(128) void prim_kernel() {
    const float INF = 1e30f;
    int b = blockIdx.x;
    const float* D = g_dist + (size_t)b * N_ * N_;
    int t = threadIdx.x, lane = t & 31, wid = t >> 5;

    __shared__ float swv[2][4];
    __shared__ int   swi[2][4];

    float md[8]; int par[8];
    {
        float4 a0 = ((const float4*)D)[2 * t];
        float4 a1 = ((const float4*)D)[2 * t + 1];
        md[0]=a0.x; md[1]=a0.y; md[2]=a0.z; md[3]=a0.w;
        md[4]=a1.x; md[5]=a1.y; md[6]=a1.z; md[7]=a1.w;
        #pragma unroll
        for (int i = 0; i < 8; i++) par[i] = 0;
    }
    unsigned tree = (t == 0) ? 1u : 0u;

    {
        float bv = INF; int bi = 0x7FFFFFFF;
        #pragma unroll
        for (int i = 0; i < 8; i++) {
            float v = ((tree >> i) & 1u) ? INF : md[i];
            if (v < bv) { bv = v; bi = 8 * t + i; }
        }
        float wv; int wi;
        warp_argmin_(bv, bi, wv, wi);
        if (lane == 0) { swv[0][wid] = wv; swi[0][wid] = wi; }
        prefetch_row_(D, wi, lane);
    }
    __syncthreads();

    for (int it = 0; it < N_ - 1; it++) {
        int s = it & 1;
        float fv = swv[s][0]; int fi = swi[s][0];
        #pragma unroll
        for (int w = 1; w < 4; w++) {
            float ov = swv[s][w]; int oi = swi[s][w];
            if (ov < fv || (ov == fv && oi < fi)) { fv = ov; fi = oi; }
        }
        int v = fi;
        if ((v >> 3) == t) {
            int sl = v & 7;
            g_parent[b * N_ + v] = par[sl];
            g_w[b * N_ + v]      = md[sl];
            tree |= (1u << sl);
        }
        const float4* rp = (const float4*)(D + (size_t)v * N_);
        float4 r0 = rp[2 * t];
        float4 r1 = rp[2 * t + 1];

        if ((v >> 8) == wid) {
            float bv2 = INF; int bi2 = 0x7FFFFFFF;
            #pragma unroll
            for (int i = 0; i < 8; i++) {
                float val = ((tree >> i) & 1u) ? INF : md[i];
                if (val < bv2) { bv2 = val; bi2 = 8 * t + i; }
            }
            float uv; int ui;
            warp_argmin_(bv2, bi2, uv, ui);
            prefetch_row_(D, ui, lane);
        }

        float r[8] = {r0.x, r0.y, r0.z, r0.w, r1.x, r1.y, r1.z, r1.w};
        #pragma unroll
        for (int i = 0; i < 8; i++)
            if (r[i] < md[i]) { md[i] = r[i]; par[i] = v; }

        float bv3 = INF; int bi3 = 0x7FFFFFFF;
        #pragma unroll
        for (int i = 0; i < 8; i++) {
            float val = ((tree >> i) & 1u) ? INF : md[i];
            if (val < bv3) { bv3 = val; bi3 = 8 * t + i; }
        }
        float wv3; int wi3;
        warp_argmin_(bv3, bi3, wv3, wi3);
        prefetch_row_(D, wi3, lane);
        if (lane == 0) { int s2 = (it + 1) & 1; swv[s2][wid] = wv3; swi[s2][wid] = wi3; }
        __syncthreads();
    }
}

// ---------------- degree / dinv / misc --------------------------------------
__global__ void deg_init() {
    int i = blockIdx.x * 256 + threadIdx.x;
    if (i < NT_) g_deg[i] = 1.0f;
}
__global__ void deg_scatter() {
    int e = blockIdx.x * 256 + threadIdx.x;
    if (e >= NT_) return;
    int v = e & (N_ - 1);
    if (v == 0) return;
    int b = e >> 10;
    float w = g_w[e];
    atomicAdd(&g_deg[e], w);
    atomicAdd(&g_deg[(b << 10) + g_parent[e]], w);
}
__global__ void dinv_kernel() {
    int i = blockIdx.x * 256 + threadIdx.x;
    if (i < NT_) g_dinv[i] = 1.0f / sqrtf(g_deg[i]);
}
__global__ void zero_pooled() {
    int i = blockIdx.x * 256 + threadIdx.x;
    if (i < B_ * F2_) g_pooled[i] = 0.f;
}

// ---------------- children CSR (built once per forward) ----------------------
__global__ void zero_csr() {
    int i = blockIdx.x * 256 + threadIdx.x;
    if (i < NT_) { g_cnt[i] = 0; g_fill[i] = 0; }
}
__global__ void count_children() {
    int e = blockIdx.x * 256 + threadIdx.x;
    if (e >= NT_) return;
    if ((e & (N_ - 1)) == 0) return;
    int gp = (e & ~(N_ - 1)) + g_parent[e];
    atomicAdd(&g_cnt[gp], 1);
}
__global__ __launch_bounds__(1024) void scan_children() {
    __shared__ int sa[1024], sb2[1024];
    int b = blockIdx.x, v = threadIdx.x;
    int gi = (b << 10) + v;
    int c = g_cnt[gi];
    sa[v] = c;
    __syncthreads();
    int *src = sa, *dst = sb2;
    for (int o = 1; o < 1024; o <<= 1) {
        dst[v] = src[v] + ((v >= o) ? src[v - o] : 0);
        __syncthreads();
        int* tmp = src; src = dst; dst = tmp;
    }
    g_off[gi] = (b << 10) + src[v] - c;    // exclusive scan, global base
}
__global__ void fill_children() {
    int e = blockIdx.x * 256 + threadIdx.x;
    if (e >= NT_) return;
    if ((e & (N_ - 1)) == 0) return;
    int gp = (e & ~(N_ - 1)) + g_parent[e];
    int pos = g_off[gp] + atomicAdd(&g_fill[gp], 1);
    g_child[pos] = e;
}

// ---------------- propagation: gather (no atomics) ---------------------------
// prop_i = dinv_i^2 * x_i + c_par * x_par + sum_children c_c * x_c
__global__ __launch_bounds__(128) void prop_gather(const float* __restrict__ x, int F) {
    int gi = blockIdx.x;
    int b = gi >> 10, v = gi & (N_ - 1);
    int t = threadIdx.x;
    float dv = g_dinv[gi];
    float cs = dv * dv;
    float acc[4];
    #pragma unroll
    for (int j = 0; j < 4; j++) {
        int f = t + j * 128;
        acc[j] = (f < F) ? cs * x[(size_t)gi * F + f] : 0.f;
    }
    if (v != 0) {
        int gp = (b << 10) + g_parent[gi];
        float cp = dv * g_w[gi] * g_dinv[gp];
        #pragma unroll
        for (int j = 0; j < 4; j++) {
            int f = t + j * 128;
            if (f < F) acc[j] += cp * x[(size_t)gp * F + f];
        }
    }
    int s0 = g_off[gi], s1 = s0 + g_cnt[gi];
    for (int k = s0; k < s1; k++) {
        int c = g_child[k];
        float cc = dv * g_w[c] * g_dinv[c];
        #pragma unroll
        for (int j = 0; j < 4; j++) {
            int f = t + j * 128;
            if (f < F) acc[j] += cc * x[(size_t)c * F + f];
        }
    }
    #pragma unroll
    for (int j = 0; j < 4; j++) {
        int f = t + j * 128;
        if (f < F) g_prop[(size_t)gi * F + f] = acc[j];
    }
}

// W[K][Nn] -> WThi/WTlo [Nn][K] (transpose + tf32 split)
__global__ void wtrans_split(const float* __restrict__ W, int K, int Nn) {
    __shared__ float t[32][33];
    int k0 = blockIdx.y * 32, n0 = blockIdx.x * 32;
    t[threadIdx.y][threadIdx.x] = W[(size_t)(k0 + threadIdx.y) * Nn + n0 + threadIdx.x];
    __syncthreads();
    float v = t[threadIdx.x][threadIdx.y];
    float hi = tf32_rna(v);
    int o = (n0 + threadIdx.y) * K + k0 + threadIdx.x;
    g_WThi[o] = hi;
    g_WTlo[o] = v - hi;
}

// ---------------- fused SSG-combine + 3xTF32 GEMM + bias + tanh --------------
__global__ __launch_bounds__(256) void gemm_fused(
    const float* __restrict__ x, const float* __restrict__ prop,
    const float* __restrict__ bias, float* __restrict__ C, int K, int Nn) {
    extern __shared__ float smem[];
    uint32_t sb = smem_u32(smem);
    int tid = threadIdx.x, lane = tid & 31, wid = tid >> 5;
    int bm = blockIdx.y * 128, bn = blockIdx.x * 128;
    int wm = (wid >> 2) * 64, wn = (wid & 3) * 32;
    int nc = K / KC_;

    int lrow[4], lk4[4];
    uint32_t ldoff[4];
    #pragma unroll
    for (int i = 0; i < 4; i++) {
        int lin = tid + i * 256;
        lrow[i] = lin >> 3; lk4[i] = lin & 7;
        ldoff[i] = (uint32_t)(lrow[i] * 128 + ((lk4[i] ^ (lrow[i] & 7)) << 4));
    }

    float4 xa[4], pa[4];

    #define ISSUE_W(c, s) do {                                                 \
        uint32_t base = sb + (s) * (STG_FLOATS * 4);                           \
        _Pragma("unroll")                                                      \
        for (int i = 0; i < 4; i++) {                                          \
            size_t gw = (size_t)(bn + lrow[i]) * K + (c) * KC_ + lk4[i] * 4;   \
            CP16(base + 32768 + ldoff[i], g_WThi + gw);                        \
            CP16(base + 49152 + ldoff[i], g_WTlo + gw);                        \
        }                                                                      \
        CP_COMMIT();                                                           \
    } while (0)

    #define ISSUE_A(c) do {                                                    \
        _Pragma("unroll")                                                      \
        for (int i = 0; i < 4; i++) {                                          \
            size_t ga = (size_t)(bm + lrow[i]) * K + (c) * KC_ + lk4[i] * 4;   \
            xa[i] = *(const float4*)&x[ga];                                    \
            pa[i] = *(const float4*)&prop[ga];                                 \
        }                                                                      \
    } while (0)

    #define STS_A(s) do {                                                      \
        _Pragma("unroll")                                                      \
        for (int i = 0; i < 4; i++) {                                          \
            float4 hi, lo;                                                     \
            float v0 = ALPHA_ * xa[i].x + (1.0f - ALPHA_) * pa[i].x;           \
            float v1 = ALPHA_ * xa[i].y + (1.0f - ALPHA_) * pa[i].y;           \
            float v2 = ALPHA_ * xa[i].z + (1.0f - ALPHA_) * pa[i].z;           \
            float v3 = ALPHA_ * xa[i].w + (1.0f - ALPHA_) * pa[i].w;           \
            hi.x = tf32_rna(v0); lo.x = v0 - hi.x;                             \
            hi.y = tf32_rna(v1); lo.y = v1 - hi.y;                             \
            hi.z = tf32_rna(v2); lo.z = v2 - hi.z;                             \
            hi.w = tf32_rna(v3); lo.w = v3 - hi.w;                             \
            char* sp = (char*)smem + (s) * (STG_FLOATS * 4) + ldoff[i];        \
            *(float4*)sp = hi;                                                 \
            *(float4*)(sp + 16384) = lo;                                       \
        }                                                                      \
    } while (0)

    float acc[4][4][4] = {};
    ISSUE_W(0, 0); ISSUE_A(0); STS_A(0);

    for (int c = 0; c < nc; c++) {
        if (c + 1 < nc) { ISSUE_W(c + 1, (c + 1) & 1); ISSUE_A(c + 1); CP_WAIT1(); }
        else            { CP_WAIT0(); }
        __syncthreads();
        mma_stage_compute((const uint32_t*)(smem + (c & 1) * STG_FLOATS), lane, wm, wn, acc);
        if (c + 1 < nc) STS_A((c + 1) & 1);
        __syncthreads();
    }

    #pragma unroll
    for (int mt = 0; mt < 4; mt++) {
        int r0 = bm + wm + mt * 16 + (lane >> 2);
        #pragma unroll
        for (int nt = 0; nt < 4; nt++) {
            int cb = bn + wn + nt * 8 + 2 * (lane & 3);
            float b0 = bias[cb], b1 = bias[cb + 1];
            float2 o0, o1;
            o0.x = tanhf(acc[mt][nt][0] + b0);
            o0.y = tanhf(acc[mt][nt][1] + b1);
            o1.x = tanhf(acc[mt][nt][2] + b0);
            o1.y = tanhf(acc[mt][nt][3] + b1);
            *(float2*)&C[(size_t)r0 * Nn + cb]       = o0;
            *(float2*)&C[(size_t)(r0 + 8) * Nn + cb] = o1;
        }
    }
}

// ---------------- pooling + head --------------------------------------------
__global__ void pool_kernel(const float* __restrict__ x) {
    int b = blockIdx.y, chunk = blockIdx.x;
    int col = threadIdx.x;
    const float* xb = x + ((size_t)b * N_ + chunk * 256) * F2_;
    float s = 0.f;
    for (int r = 0; r < 256; r++) s += xb[(size_t)r * F2_ + col];
    atomicAdd(&g_pooled[b * F2_ + col], s);
}

__global__ __launch_bounds__(256) void head_dense(
    const float* __restrict__ Wd, const float* __restrict__ bd,
    const float* __restrict__ Wo, const float* __restrict__ bo,
    float* __restrict__ out) {
    int b = blockIdx.x, t = threadIdx.x;
    __shared__ float pl[F2_];
    __shared__ float hd[H_];
    for (int i = t; i < F2_; i += 256)
        pl[i] = g_pooled[b * F2_ + i] * (1.0f / (float)N_);
    __syncthreads();
    float acc = bd[t];
    for (int k = 0; k < F2_; k++) acc += pl[k] * Wd[k * H_ + t];
    hd[t] = tanhf(acc);
    __syncthreads();
    if (t < 8) {
        float a = bo[t];
        for (int k = 0; k < H_; k++) a += hd[k] * Wo[k * 8 + t];
        out[b * 8 + t] = a;
    }
}

// ---------------- launch ----------------------------------------------------
extern "C" void kernel_launch(void* const* d_in, const int* in_sizes, int n_in,
                              void* d_out, int out_size) {
    const float* features = (const float*)d_in[0];
    const float* W1 = (const float*)d_in[1];
    const float* b1 = (const float*)d_in[2];
    const float* W2 = (const float*)d_in[3];
    const float* b2 = (const float*)d_in[4];
    const float* W3 = (const float*)d_in[5];
    const float* b3 = (const float*)d_in[6];
    const float* Wd = (const float*)d_in[7];
    const float* bd = (const float*)d_in[8];
    const float* Wo = (const float*)d_in[9];
    const float* bo = (const float*)d_in[10];
    float* out = (float*)d_out;

    void *p_prop_v, *p_bufA_v, *p_bufB_v;
    cudaGetSymbolAddress(&p_prop_v, g_prop);
    cudaGetSymbolAddress(&p_bufA_v, g_bufA);
    cudaGetSymbolAddress(&p_bufB_v, g_bufB);
    float* p_prop = (float*)p_prop_v;
    float* p_bufA = (float*)p_bufA_v;
    float* p_bufB = (float*)p_bufB_v;

    cudaFuncSetAttribute(gemm_fused, cudaFuncAttributeMaxDynamicSharedMemorySize, GEMM_SMEM);
    cudaFuncSetAttribute(dist_mma, cudaFuncAttributeMaxDynamicSharedMemorySize, GEMM_SMEM);

    // launch order: #4 (prim_kernel) gets profiled by ncu
    norms_kernel<<<NT_ / 8, 256>>>(features, 0);                   // 1
    xsplit<<<(NT_ * H_ / 4 + 255) / 256, 256>>>(features);         // 2
    dist_mma<<<dim3(8, 8, B_), 256, GEMM_SMEM>>>();                // 3
    prim_kernel<<<B_, 128>>>();                                    // 4 <- profiled
    zero_pooled<<<(B_ * F2_) / 256, 256>>>();                      // 5
    deg_init<<<NT_ / 256, 256>>>();
    deg_scatter<<<NT_ / 256, 256>>>();
    dinv_kernel<<<NT_ / 256, 256>>>();
    zero_csr<<<NT_ / 256, 256>>>();
    count_children<<<NT_ / 256, 256>>>();
    scan_children<<<B_, 1024>>>();
    fill_children<<<NT_ / 256, 256>>>();

    // layer 1: features [NT,256] -> bufA [NT,512]
    prop_gather<<<NT_, 128>>>(features, H_);
    wtrans_split<<<dim3(F2_ / 32, H_ / 32), dim3(32, 32)>>>(W1, H_, F2_);
    gemm_fused<<<dim3(F2_ / 128, NT_ / 128), 256, GEMM_SMEM>>>(features, p_prop, b1, p_bufA, H_, F2_);

    // layer 2: bufA -> bufB
    prop_gather<<<NT_, 128>>>(p_bufA, F2_);
    wtrans_split<<<dim3(F2_ / 32, F2_ / 32), dim3(32, 32)>>>(W2, F2_, F2_);
    gemm_fused<<<dim3(F2_ / 128, NT_ / 128), 256, GEMM_SMEM>>>(p_bufA, p_prop, b2, p_bufB, F2_, F2_);

    // layer 3: bufB -> bufA
    prop_gather<<<NT_, 128>>>(p_bufB, F2_);
    wtrans_split<<<dim3(F2_ / 32, F2_ / 32), dim3(32, 32)>>>(W3, F2_, F2_);
    gemm_fused<<<dim3(F2_ / 128, NT_ / 128), 256, GEMM_SMEM>>>(p_bufB, p_prop, b3, p_bufA, F2_, F2_);

    // head
    pool_kernel<<<dim3(4, B_), F2_>>>(p_bufA);
    head_dense<<<B_, 256>>>(Wd, bd, Wo, bo, out);
}

// round 15
// speedup vs baseline: 1.0638x; 1.0638x over previous
#include <cuda_runtime.h>
#include <math.h>
#include <stdint.h>

#define B_    16
#define N_    1024
#define H_    256
#define NT_   (B_ * N_)
#define F2_   512
#define ALPHA_ 0.3f

// ---------------- scratch ---------------------------------------------------
__device__ float g_dist[(size_t)B_ * N_ * N_];   // 64 MB
__device__ float g_n2[NT_];
__device__ int   g_parent[NT_];
__device__ float g_w[NT_];
__device__ float g_deg[NT_];
__device__ float g_dinv[NT_];
__device__ float g_prop[(size_t)NT_ * F2_];      // 32 MB
__device__ float g_bufA[(size_t)NT_ * F2_];      // 32 MB
__device__ float g_bufB[(size_t)NT_ * F2_];      // 32 MB
__device__ float g_Xhi[(size_t)NT_ * H_];        // 16 MB (tf32-split features)
__device__ float g_Xlo[(size_t)NT_ * H_];        // 16 MB
__device__ float g_WThi[F2_ * F2_];              // WT[N][K]
__device__ float g_WTlo[F2_ * F2_];
__device__ float g_pooled[B_ * F2_];

// ---------------- helpers ----------------------------------------------------
__device__ __forceinline__ uint32_t smem_u32(const void* p) {
    uint32_t a;
    asm("{ .reg .u64 t; cvta.to.shared.u64 t, %1; cvt.u32.u64 %0, t; }" : "=r"(a) : "l"(p));
    return a;
}
__device__ __forceinline__ float tf32_rna(float v) {
    uint32_t r;
    asm("cvt.rna.tf32.f32 %0, %1;" : "=r"(r) : "f"(v));
    return __uint_as_float(r);
}
__device__ __forceinline__ uint32_t redux_min_u32(uint32_t v) {
    uint32_t r;
    asm("redux.sync.min.u32 %0, %1, 0xffffffff;" : "=r"(r) : "r"(v));
    return r;
}
#define CP16(dst, src) asm volatile("cp.async.cg.shared.global [%0], [%1], 16;" :: "r"(dst), "l"(src))
#define CP_COMMIT()    asm volatile("cp.async.commit_group;" ::: "memory")
#define CP_WAIT1()     asm volatile("cp.async.wait_group 1;" ::: "memory")
#define CP_WAIT0()     asm volatile("cp.async.wait_group 0;" ::: "memory")

#define MMA_TF32(d, a, b) \
    asm volatile("mma.sync.aligned.m16n8k8.row.col.f32.tf32.tf32.f32 " \
        "{%0,%1,%2,%3}, {%4,%5,%6,%7}, {%8,%9}, {%0,%1,%2,%3};" \
        : "+f"((d)[0]), "+f"((d)[1]), "+f"((d)[2]), "+f"((d)[3]) \
        : "r"((a)[0]), "r"((a)[1]), "r"((a)[2]), "r"((a)[3]), "r"((b)[0]), "r"((b)[1]))

__device__ __forceinline__ uint32_t tile_ld(const uint32_t* base, int row, int k) {
    return base[row * 32 + (((k >> 2) ^ (row & 7)) << 2) + (k & 3)];
}

#define KC_ 32
#define STG_FLOATS 16384
#define GEMM_SMEM  (2 * STG_FLOATS * 4)

__device__ __forceinline__ void mma_stage_compute(
    const uint32_t* st, int lane, int wm, int wn, float acc[4][4][4]) {
    const uint32_t* sAhi = st;
    const uint32_t* sAlo = st + 4096;
    const uint32_t* sWhi = st + 8192;
    const uint32_t* sWlo = st + 12288;
    #pragma unroll
    for (int kk = 0; kk < 4; kk++) {
        int ck = kk * 8 + (lane & 3);
        uint32_t ah[4][4], al[4][4];
        #pragma unroll
        for (int mt = 0; mt < 4; mt++) {
            int m = wm + mt * 16 + (lane >> 2);
            ah[mt][0] = tile_ld(sAhi, m,     ck);
            ah[mt][1] = tile_ld(sAhi, m + 8, ck);
            ah[mt][2] = tile_ld(sAhi, m,     ck + 4);
            ah[mt][3] = tile_ld(sAhi, m + 8, ck + 4);
            al[mt][0] = tile_ld(sAlo, m,     ck);
            al[mt][1] = tile_ld(sAlo, m + 8, ck);
            al[mt][2] = tile_ld(sAlo, m,     ck + 4);
            al[mt][3] = tile_ld(sAlo, m + 8, ck + 4);
        }
        uint32_t bh[4][2], bl[4][2];
        #pragma unroll
        for (int nt = 0; nt < 4; nt++) {
            int n = wn + nt * 8 + (lane >> 2);
            bh[nt][0] = tile_ld(sWhi, n, ck);
            bh[nt][1] = tile_ld(sWhi, n, ck + 4);
            bl[nt][0] = tile_ld(sWlo, n, ck);
            bl[nt][1] = tile_ld(sWlo, n, ck + 4);
        }
        #pragma unroll
        for (int mt = 0; mt < 4; mt++)
            #pragma unroll
            for (int nt = 0; nt < 4; nt++) {
                MMA_TF32(acc[mt][nt], ah[mt], bh[nt]);
                MMA_TF32(acc[mt][nt], ah[mt], bl[nt]);
                MMA_TF32(acc[mt][nt], al[mt], bh[nt]);
            }
    }
}

// ---------------- row norms -------------------------------------------------
__global__ void norms_kernel(const float* __restrict__ X, int row0) {
    int row  = row0 + blockIdx.x * 8 + (threadIdx.x >> 5);
    int lane = threadIdx.x & 31;
    const float* r = X + (size_t)row * H_;
    float s = 0.f;
    #pragma unroll
    for (int i = lane; i < H_; i += 32) { float v = r[i]; s += v * v; }
    #pragma unroll
    for (int o = 16; o; o >>= 1) s += __shfl_down_sync(0xffffffffu, s, o);
    if (lane == 0) g_n2[row] = s;
}

// ---------------- features tf32 split ---------------------------------------
__global__ void xsplit(const float* __restrict__ X) {
    size_t i = (size_t)blockIdx.x * 256 + threadIdx.x;
    if (i >= (size_t)NT_ * H_ / 4) return;
    float4 v = ((const float4*)X)[i];
    float4 hi, lo;
    hi.x = tf32_rna(v.x); lo.x = v.x - hi.x;
    hi.y = tf32_rna(v.y); lo.y = v.y - hi.y;
    hi.z = tf32_rna(v.z); lo.z = v.z - hi.z;
    hi.w = tf32_rna(v.w); lo.w = v.w - hi.w;
    ((float4*)g_Xhi)[i] = hi;
    ((float4*)g_Xlo)[i] = lo;
}

// ---------------- distance matrix via 3xTF32 MMA ----------------------------
__global__ __launch_bounds__(256) void dist_mma() {
    if (blockIdx.x > blockIdx.y) return;
    extern __shared__ float smem[];
    uint32_t sb = smem_u32(smem);
    int b = blockIdx.z;
    int tid = threadIdx.x, lane = tid & 31, wid = tid >> 5;
    int bm = blockIdx.y * 128, bn = blockIdx.x * 128;
    int wm = (wid >> 2) * 64, wn = (wid & 3) * 32;
    size_t rowA = (size_t)b * N_ + bm;
    size_t rowB = (size_t)b * N_ + bn;
    int nc = H_ / KC_;

    int lrow[4], lk4[4];
    uint32_t ldoff[4];
    #pragma unroll
    for (int i = 0; i < 4; i++) {
        int lin = tid + i * 256;
        lrow[i] = lin >> 3; lk4[i] = lin & 7;
        ldoff[i] = (uint32_t)(lrow[i] * 128 + ((lk4[i] ^ (lrow[i] & 7)) << 4));
    }

    #define LOAD_CHUNK_D(c, s) do {                                            \
        uint32_t base = sb + (s) * (STG_FLOATS * 4);                           \
        _Pragma("unroll")                                                      \
        for (int i = 0; i < 4; i++) {                                          \
            size_t ga = (rowA + lrow[i]) * H_ + (c) * KC_ + lk4[i] * 4;        \
            size_t gb = (rowB + lrow[i]) * H_ + (c) * KC_ + lk4[i] * 4;        \
            CP16(base +         ldoff[i], g_Xhi + ga);                         \
            CP16(base + 16384 + ldoff[i], g_Xlo + ga);                         \
            CP16(base + 32768 + ldoff[i], g_Xhi + gb);                         \
            CP16(base + 49152 + ldoff[i], g_Xlo + gb);                         \
        }                                                                      \
        CP_COMMIT();                                                           \
    } while (0)

    float acc[4][4][4] = {};
    LOAD_CHUNK_D(0, 0);
    for (int c = 0; c < nc; c++) {
        if (c + 1 < nc) { LOAD_CHUNK_D(c + 1, (c + 1) & 1); CP_WAIT1(); }
        else            { CP_WAIT0(); }
        __syncthreads();
        mma_stage_compute((const uint32_t*)(smem + (c & 1) * STG_FLOATS), lane, wm, wn, acc);
        __syncthreads();
    }

    const float* n2b = g_n2 + b * N_;
    float* Db = g_dist + (size_t)b * N_ * N_;
    #pragma unroll
    for (int mt = 0; mt < 4; mt++) {
        int r0 = bm + wm + mt * 16 + (lane >> 2);
        float ni0 = n2b[r0], ni1 = n2b[r0 + 8];
        #pragma unroll
        for (int nt = 0; nt < 4; nt++) {
            int cb = bn + wn + nt * 8 + 2 * (lane & 3);
            float nj0 = n2b[cb], nj1 = n2b[cb + 1];
            float d00 = sqrtf(fmaxf(ni0 + nj0 - 2.0f * acc[mt][nt][0], 0.0f));
            float d01 = sqrtf(fmaxf(ni0 + nj1 - 2.0f * acc[mt][nt][1], 0.0f));
            float d10 = sqrtf(fmaxf(ni1 + nj0 - 2.0f * acc[mt][nt][2], 0.0f));
            float d11 = sqrtf(fmaxf(ni1 + nj1 - 2.0f * acc[mt][nt][3], 0.0f));
            *(float2*)&Db[(size_t)r0 * N_ + cb]       = make_float2(d00, d01);
            *(float2*)&Db[(size_t)(r0 + 8) * N_ + cb] = make_float2(d10, d11);
            if (blockIdx.x != blockIdx.y) {
                Db[(size_t)cb * N_ + r0]           = d00;
                Db[(size_t)(cb + 1) * N_ + r0]     = d01;
                Db[(size_t)cb * N_ + r0 + 8]       = d10;
                Db[(size_t)(cb + 1) * N_ + r0 + 8] = d11;
            }
        }
    }
}

// ---------------- Prim MST v6: no winner-warp recompute, fast local argmin ---
__device__ __forceinline__ void warp_argmin_(float bv, int bi, float& wv, int& wi) {
    uint32_t vb = __float_as_uint(bv);
    uint32_t wmin = redux_min_u32(vb);
    uint32_t m = __ballot_sync(0xffffffffu, vb == wmin);
    int src = __ffs(m) - 1;
    wv = __uint_as_float(wmin);
    wi = __shfl_sync(0xffffffffu, bi, src);
}
__device__ __forceinline__ void prefetch_row_(const float* D, int v, int lane) {
    if ((unsigned)v >= (unsigned)N_) return;
    const char* p = (const char*)(D + (size_t)v * N_) + lane * 32;
    asm volatile("prefetch.global.L1 [%0];" :: "l"(p));
    asm volatile("prefetch.global.L1 [%0];" :: "l"(p + 1024));
    asm volatile("prefetch.global.L1 [%0];" :: "l"(p + 2048));
    asm volatile("prefetch.global.L1 [%0];" :: "l"(p + 3072));
}

__global__ __launch_bounds__(128) void prim_kernel() {
    const float INF = 1e30f;
    int b = blockIdx.x;
    const float* D = g_dist + (size_t)b * N_ * N_;
    int t = threadIdx.x, lane = t & 31, wid = t >> 5;

    __shared__ float swv[2][4];
    __shared__ int   swi[2][4];

    float md[8]; int par[8];
    {
        float4 a0 = ((const float4*)D)[2 * t];
        float4 a1 = ((const float4*)D)[2 * t + 1];
        md[0]=a0.x; md[1]=a0.y; md[2]=a0.z; md[3]=a0.w;
        md[4]=a1.x; md[5]=a1.y; md[6]=a1.z; md[7]=a1.w;
        #pragma unroll
        for (int i = 0; i < 8; i++) par[i] = 0;
    }
    unsigned tree = (t == 0) ? 1u : 0u;

    {
        float bv = INF; int bi = 0x7FFFFFFF;
        #pragma unroll
        for (int i = 0; i < 8; i++) {
            float v = ((tree >> i) & 1u) ? INF : md[i];
            if (v < bv) { bv = v; bi = 8 * t + i; }
        }
        float wv; int wi;
        warp_argmin_(bv, bi, wv, wi);
        if (lane == 0) { swv[0][wid] = wv; swi[0][wid] = wi; }
        prefetch_row_(D, wi, lane);
    }
    __syncthreads();

    for (int it = 0; it < N_ - 1; it++) {
        int s = it & 1;
        // combine the 4 per-warp candidates (ordered => exact lowest-index argmin)
        float fv = swv[s][0]; int fi = swi[s][0];
        #pragma unroll
        for (int w = 1; w < 4; w++) {
            float ov = swv[s][w]; int oi = swi[s][w];
            if (ov < fv || (ov == fv && oi < fi)) { fv = ov; fi = oi; }
        }
        int v = fi;
        if ((v >> 3) == t) {                      // owner records the MST edge
            int sl = v & 7;
            g_parent[b * N_ + v] = par[sl];
            g_w[b * N_ + v]      = md[sl];
            tree |= (1u << sl);
        }
        // row load (prefetched to L1 last iteration: v is one of the 4 candidates)
        const float4* rp = (const float4*)(D + (size_t)v * N_);
        float4 r0 = rp[2 * t];
        float4 r1 = rp[2 * t + 1];

        // update
        float r[8] = {r0.x, r0.y, r0.z, r0.w, r1.x, r1.y, r1.z, r1.w};
        #pragma unroll
        for (int i = 0; i < 8; i++)
            if (r[i] < md[i]) { md[i] = r[i]; par[i] = v; }

        // local argmin: fminf tree + equality mask + ffs (lowest index exact)
        float q[8];
        #pragma unroll
        for (int i = 0; i < 8; i++)
            q[i] = ((tree >> i) & 1u) ? INF : md[i];
        float m01 = fminf(q[0], q[1]), m23 = fminf(q[2], q[3]);
        float m45 = fminf(q[4], q[5]), m67 = fminf(q[6], q[7]);
        float nbv = fminf(fminf(m01, m23), fminf(m45, m67));
        uint32_t mask = 0u;
        #pragma unroll
        for (int i = 0; i < 8; i++)
            if (q[i] == nbv) mask |= (1u << i);
        int nbi = 8 * t + (__ffs(mask) - 1);

        float wv; int wi;
        warp_argmin_(nbv, nbi, wv, wi);
        prefetch_row_(D, wi, lane);
        if (lane == 0) { int s2 = (it + 1) & 1; swv[s2][wid] = wv; swi[s2][wid] = wi; }
        __syncthreads();
    }
}

// ---------------- degree / dinv / misc --------------------------------------
__global__ void deg_init() {
    int i = blockIdx.x * 256 + threadIdx.x;
    if (i < NT_) g_deg[i] = 1.0f;
}
__global__ void deg_scatter() {
    int e = blockIdx.x * 256 + threadIdx.x;
    if (e >= NT_) return;
    int v = e & (N_ - 1);
    if (v == 0) return;
    int b = e >> 10;
    float w = g_w[e];
    atomicAdd(&g_deg[e], w);
    atomicAdd(&g_deg[(b << 10) + g_parent[e]], w);
}
__global__ void dinv_kernel() {
    int i = blockIdx.x * 256 + threadIdx.x;
    if (i < NT_) g_dinv[i] = 1.0f / sqrtf(g_deg[i]);
}
__global__ void zero_pooled() {
    int i = blockIdx.x * 256 + threadIdx.x;
    if (i < B_ * F2_) g_pooled[i] = 0.f;
}

// ---------------- propagation (scatter-atomics, R12 config) ------------------
__global__ void prop_init(const float* __restrict__ x, int log2F) {
    size_t i = (size_t)blockIdx.x * blockDim.x + threadIdx.x;
    size_t total = ((size_t)NT_ << log2F) >> 2;
    if (i >= total) return;
    int node = (int)((i << 2) >> log2F);
    float d = g_dinv[node];
    float c = d * d;
    float4 xv = ((const float4*)x)[i];
    float4 o;
    o.x = c * xv.x; o.y = c * xv.y; o.z = c * xv.z; o.w = c * xv.w;
    ((float4*)g_prop)[i] = o;
}

__global__ void edge_scatter(const float* __restrict__ x, int F) {
    int e = blockIdx.x;
    int v = e & (N_ - 1);
    if (v == 0) return;
    int b = e >> 10;
    int gv = e;
    int gp = (b << 10) + g_parent[e];
    float c = g_dinv[gp] * g_w[e] * g_dinv[gv];
    const float* xp = x + (size_t)gp * F;
    const float* xv = x + (size_t)gv * F;
    float* pv = g_prop + (size_t)gv * F;
    float* pp = g_prop + (size_t)gp * F;
    for (int f = threadIdx.x; f < F; f += blockDim.x) {
        atomicAdd(&pv[f], c * xp[f]);
        atomicAdd(&pp[f], c * xv[f]);
    }
}

// W[K][Nn] -> WThi/WTlo [Nn][K] (transpose + tf32 split)
__global__ void wtrans_split(const float* __restrict__ W, int K, int Nn) {
    __shared__ float t[32][33];
    int k0 = blockIdx.y * 32, n0 = blockIdx.x * 32;
    t[threadIdx.y][threadIdx.x] = W[(size_t)(k0 + threadIdx.y) * Nn + n0 + threadIdx.x];
    __syncthreads();
    float v = t[threadIdx.x][threadIdx.y];
    float hi = tf32_rna(v);
    int o = (n0 + threadIdx.y) * K + k0 + threadIdx.x;
    g_WThi[o] = hi;
    g_WTlo[o] = v - hi;
}

// ---------------- fused SSG-combine + 3xTF32 GEMM + bias + tanh --------------
__global__ __launch_bounds__(256) void gemm_fused(
    const float* __restrict__ x, const float* __restrict__ prop,
    const float* __restrict__ bias, float* __restrict__ C, int K, int Nn) {
    extern __shared__ float smem[];
    uint32_t sb = smem_u32(smem);
    int tid = threadIdx.x, lane = tid & 31, wid = tid >> 5;
    int bm = blockIdx.y * 128, bn = blockIdx.x * 128;
    int wm = (wid >> 2) * 64, wn = (wid & 3) * 32;
    int nc = K / KC_;

    int lrow[4], lk4[4];
    uint32_t ldoff[4];
    #pragma unroll
    for (int i = 0; i < 4; i++) {
        int lin = tid + i * 256;
        lrow[i] = lin >> 3; lk4[i] = lin & 7;
        ldoff[i] = (uint32_t)(lrow[i] * 128 + ((lk4[i] ^ (lrow[i] & 7)) << 4));
    }

    float4 xa[4], pa[4];

    #define ISSUE_W(c, s) do {                                                 \
        uint32_t base = sb + (s) * (STG_FLOATS * 4);                           \
        _Pragma("unroll")                                                      \
        for (int i = 0; i < 4; i++) {                                          \
            size_t gw = (size_t)(bn + lrow[i]) * K + (c) * KC_ + lk4[i] * 4;   \
            CP16(base + 32768 + ldoff[i], g_WThi + gw);                        \
            CP16(base + 49152 + ldoff[i], g_WTlo + gw);                        \
        }                                                                      \
        CP_COMMIT();                                                           \
    } while (0)

    #define ISSUE_A(c) do {                                                    \
        _Pragma("unroll")                                                      \
        for (int i = 0; i < 4; i++) {                                          \
            size_t ga = (size_t)(bm + lrow[i]) * K + (c) * KC_ + lk4[i] * 4;   \
            xa[i] = *(const float4*)&x[ga];                                    \
            pa[i] = *(const float4*)&prop[ga];                                 \
        }                                                                      \
    } while (0)

    #define STS_A(s) do {                                                      \
        _Pragma("unroll")                                                      \
        for (int i = 0; i < 4; i++) {                                          \
            float4 hi, lo;                                                     \
            float v0 = ALPHA_ * xa[i].x + (1.0f - ALPHA_) * pa[i].x;           \
            float v1 = ALPHA_ * xa[i].y + (1.0f - ALPHA_) * pa[i].y;           \
            float v2 = ALPHA_ * xa[i].z + (1.0f - ALPHA_) * pa[i].z;           \
            float v3 = ALPHA_ * xa[i].w + (1.0f - ALPHA_) * pa[i].w;           \
            hi.x = tf32_rna(v0); lo.x = v0 - hi.x;                             \
            hi.y = tf32_rna(v1); lo.y = v1 - hi.y;                             \
            hi.z = tf32_rna(v2); lo.z = v2 - hi.z;                             \
            hi.w = tf32_rna(v3); lo.w = v3 - hi.w;                             \
            char* sp = (char*)smem + (s) * (STG_FLOATS * 4) + ldoff[i];        \
            *(float4*)sp = hi;                                                 \
            *(float4*)(sp + 16384) = lo;                                       \
        }                                                                      \
    } while (0)

    float acc[4][4][4] = {};
    ISSUE_W(0, 0); ISSUE_A(0); STS_A(0);

    for (int c = 0; c < nc; c++) {
        if (c + 1 < nc) { ISSUE_W(c + 1, (c + 1) & 1); ISSUE_A(c + 1); CP_WAIT1(); }
        else            { CP_WAIT0(); }
        __syncthreads();
        mma_stage_compute((const uint32_t*)(smem + (c & 1) * STG_FLOATS), lane, wm, wn, acc);
        if (c + 1 < nc) STS_A((c + 1) & 1);
        __syncthreads();
    }

    #pragma unroll
    for (int mt = 0; mt < 4; mt++) {
        int r0 = bm + wm + mt * 16 + (lane >> 2);
        #pragma unroll
        for (int nt = 0; nt < 4; nt++) {
            int cb = bn + wn + nt * 8 + 2 * (lane & 3);
            float b0 = bias[cb], b1 = bias[cb + 1];
            float2 o0, o1;
            o0.x = tanhf(acc[mt][nt][0] + b0);
            o0.y = tanhf(acc[mt][nt][1] + b1);
            o1.x = tanhf(acc[mt][nt][2] + b0);
            o1.y = tanhf(acc[mt][nt][3] + b1);
            *(float2*)&C[(size_t)r0 * Nn + cb]       = o0;
            *(float2*)&C[(size_t)(r0 + 8) * Nn + cb] = o1;
        }
    }
}

// ---------------- pooling + head --------------------------------------------
__global__ void pool_kernel(const float* __restrict__ x) {
    int b = blockIdx.y, chunk = blockIdx.x;
    int col = threadIdx.x;
    const float* xb = x + ((size_t)b * N_ + chunk * 256) * F2_;
    float s = 0.f;
    for (int r = 0; r < 256; r++) s += xb[(size_t)r * F2_ + col];
    atomicAdd(&g_pooled[b * F2_ + col], s);
}

__global__ __launch_bounds__(256) void head_dense(
    const float* __restrict__ Wd, const float* __restrict__ bd,
    const float* __restrict__ Wo, const float* __restrict__ bo,
    float* __restrict__ out) {
    int b = blockIdx.x, t = threadIdx.x;
    __shared__ float pl[F2_];
    __shared__ float hd[H_];
    for (int i = t; i < F2_; i += 256)
        pl[i] = g_pooled[b * F2_ + i] * (1.0f / (float)N_);
    __syncthreads();
    float acc = bd[t];
    for (int k = 0; k < F2_; k++) acc += pl[k] * Wd[k * H_ + t];
    hd[t] = tanhf(acc);
    __syncthreads();
    if (t < 8) {
        float a = bo[t];
        for (int k = 0; k < H_; k++) a += hd[k] * Wo[k * 8 + t];
        out[b * 8 + t] = a;
    }
}

// ---------------- launch ----------------------------------------------------
extern "C" void kernel_launch(void* const* d_in, const int* in_sizes, int n_in,
                              void* d_out, int out_size) {
    const float* features = (const float*)d_in[0];
    const float* W1 = (const float*)d_in[1];
    const float* b1 = (const float*)d_in[2];
    const float* W2 = (const float*)d_in[3];
    const float* b2 = (const float*)d_in[4];
    const float* W3 = (const float*)d_in[5];
    const float* b3 = (const float*)d_in[6];
    const float* Wd = (const float*)d_in[7];
    const float* bd = (const float*)d_in[8];
    const float* Wo = (const float*)d_in[9];
    const float* bo = (const float*)d_in[10];
    float* out = (float*)d_out;

    void *p_prop_v, *p_bufA_v, *p_bufB_v;
    cudaGetSymbolAddress(&p_prop_v, g_prop);
    cudaGetSymbolAddress(&p_bufA_v, g_bufA);
    cudaGetSymbolAddress(&p_bufB_v, g_bufB);
    float* p_prop = (float*)p_prop_v;
    float* p_bufA = (float*)p_bufA_v;
    float* p_bufB = (float*)p_bufB_v;

    cudaFuncSetAttribute(gemm_fused, cudaFuncAttributeMaxDynamicSharedMemorySize, GEMM_SMEM);
    cudaFuncSetAttribute(dist_mma, cudaFuncAttributeMaxDynamicSharedMemorySize, GEMM_SMEM);

    // launch order: #4 (prim_kernel) gets profiled by ncu
    norms_kernel<<<NT_ / 8, 256>>>(features, 0);                   // 1
    xsplit<<<(NT_ * H_ / 4 + 255) / 256, 256>>>(features);         // 2
    dist_mma<<<dim3(8, 8, B_), 256, GEMM_SMEM>>>();                // 3
    prim_kernel<<<B_, 128>>>();                                    // 4 <- profiled
    zero_pooled<<<(B_ * F2_) / 256, 256>>>();                      // 5
    deg_init<<<NT_ / 256, 256>>>();
    deg_scatter<<<NT_ / 256, 256>>>();
    dinv_kernel<<<NT_ / 256, 256>>>();

    // layer 1: features [NT,256] -> bufA [NT,512]
    {
        int nb = (NT_ * H_ / 4 + 255) / 256;
        prop_init<<<nb, 256>>>(features, 8);
        edge_scatter<<<NT_, 128>>>(features, H_);
        wtrans_split<<<dim3(F2_ / 32, H_ / 32), dim3(32, 32)>>>(W1, H_, F2_);
        gemm_fused<<<dim3(F2_ / 128, NT_ / 128), 256, GEMM_SMEM>>>(features, p_prop, b1, p_bufA, H_, F2_);
    }
    // layer 2: bufA -> bufB
    {
        int nb = (NT_ * F2_ / 4 + 255) / 256;
        prop_init<<<nb, 256>>>(p_bufA, 9);
        edge_scatter<<<NT_, 128>>>(p_bufA, F2_);
        wtrans_split<<<dim3(F2_ / 32, F2_ / 32), dim3(32, 32)>>>(W2, F2_, F2_);
        gemm_fused<<<dim3(F2_ / 128, NT_ / 128), 256, GEMM_SMEM>>>(p_bufA, p_prop, b2, p_bufB, F2_, F2_);
    }
    // layer 3: bufB -> bufA
    {
        int nb = (NT_ * F2_ / 4 + 255) / 256;
        prop_init<<<nb, 256>>>(p_bufB, 9);
        edge_scatter<<<NT_, 128>>>(p_bufB, F2_);
        wtrans_split<<<dim3(F2_ / 32, F2_ / 32), dim3(32, 32)>>>(W3, F2_, F2_);
        gemm_fused<<<dim3(F2_ / 128, NT_ / 128), 256, GEMM_SMEM>>>(p_bufB, p_prop, b3, p_bufA, F2_, F2_);
    }

    // head
    pool_kernel<<<dim3(4, B_), F2_>>>(p_bufA);
    head_dense<<<B_, 256>>>(Wd, bd, Wo, bo, out);
}